// round 16
// baseline (speedup 1.0000x reference)
#include <cuda_runtime.h>
#include <cuda_fp16.h>
#include <math.h>
#include <stdint.h>

// Problem constants
#define BB 8192
#define NN 256
#define HH 2048
#define N2 512
#define LOG2PI 1.8378770664093453f

// Smem: BK=32. Tile rows padded to 40 halves (80B): r*80 mod 128 covers all
// eight 16B chunks -> ldmatrix conflict-free, 16B-aligned.
#define ASTR 40
#define ROWB 80
#define AB_BYTES (128 * ROWB)           // 10240 per operand tile
#define STAGE_BYTES (2 * AB_BYTES)      // 20480
#define NSTAGE 4
#define SMEM_BYTES (NSTAGE * STAGE_BYTES)   // 81920

// Scratch (static __device__ — no runtime allocation)
__device__ __half g_h[BB * HH];     // tanh(x@W1+b1), fp16
__device__ float  g_f[BB * N2];     // [mu | logvar], fp32
__device__ __half g_muh[BB * NN];   // fp16 copy of mu (dense, lda=256)
__device__ float  g_ux[BB * NN];
__device__ float  g_umu[BB * NN];
__device__ float  g_rowlogp[BB];
__device__ __half g_xh[BB * NN];    // fp16 x
__device__ __half g_W1t[HH * NN];   // W1^T [2048,256]
__device__ __half g_W2t[N2 * HH];   // W2^T [512,2048]
__device__ __half g_Wvt[NN * NN];   // Wv^T [256,256]

// ---------------------------------------------------------------------------
__device__ __forceinline__ void mma_f16(float (&c)[4],
    uint32_t a0, uint32_t a1, uint32_t a2, uint32_t a3,
    uint32_t b0, uint32_t b1)
{
    asm volatile(
        "mma.sync.aligned.m16n8k16.row.col.f32.f16.f16.f32 "
        "{%0,%1,%2,%3}, {%4,%5,%6,%7}, {%8,%9}, {%0,%1,%2,%3};"
        : "+f"(c[0]), "+f"(c[1]), "+f"(c[2]), "+f"(c[3])
        : "r"(a0), "r"(a1), "r"(a2), "r"(a3), "r"(b0), "r"(b1));
}

__device__ __forceinline__ void ldsm_x4(uint32_t (&r)[4], uint32_t addr)
{
    asm volatile(
        "ldmatrix.sync.aligned.m8n8.x4.shared.b16 {%0,%1,%2,%3}, [%4];"
        : "=r"(r[0]), "=r"(r[1]), "=r"(r[2]), "=r"(r[3]) : "r"(addr));
}

__device__ __forceinline__ void cpasync16(uint32_t dst_smem, const void* src) {
    asm volatile("cp.async.cg.shared.global [%0], [%1], 16;"
                 :: "r"(dst_smem), "l"(src));
}

__device__ __forceinline__ uint32_t smem_u32(const void* p) {
    uint32_t a;
    asm("{ .reg .u64 t; cvta.to.shared.u64 t, %1; cvt.u32.u64 %0, t; }"
        : "=r"(a) : "l"(p));
    return a;
}

// ---------------------------------------------------------------------------
// fp16 MMA GEMM body. Block 128x128, BK=32, 8 warps, warp tile 64x32.
// 4-stage cp.async ring, wait_group 2, one barrier per iteration.
// MODE: 0 = h (bias+tanh, fp16), 1 = ux (fp32), 2 = f (bias, fp32 + fp16 mu),
//       3 = umu (fp32)
// ---------------------------------------------------------------------------
struct GCfg {
    const __half* A;  int lda;
    const __half* Bt; int ldbt;
    const float* bias;
    int bn, K;
};

template<int MODE>
__device__ __forceinline__ void gemm_body(const GCfg& g)
{
    extern __shared__ char smem[];
    const uint32_t sbase = smem_u32(smem);
    const int tid  = threadIdx.x;
    const int lane = tid & 31;
    const int w    = tid >> 5;
    const int wm   = (w >> 2) * 64;
    const int wn   = (w & 3) * 32;
    const int bm   = blockIdx.y * 128;
    const int lr   = lane >> 2;
    const int lc   = lane & 3;
    const int nIter = g.K / 32;

    // ldmatrix per-lane offsets (bytes within a stage)
    const int a_row = (lane & 7) + ((lane >> 3) & 1) * 8;
    const int a_k   = ((lane >> 4) & 1) * 8;
    uint32_t a_off[4];
    #pragma unroll
    for (int mt = 0; mt < 4; mt++)
        a_off[mt] = (uint32_t)(((wm + mt * 16 + a_row) * ASTR + a_k) * 2);
    const int b_row = ((lane >> 4) & 1) * 8 + (lane & 7);
    const int b_k   = ((lane >> 3) & 1) * 8;
    uint32_t b_off[2];
    #pragma unroll
    for (int p = 0; p < 2; p++)
        b_off[p] = (uint32_t)(AB_BYTES + ((wn + p * 16 + b_row) * ASTR + b_k) * 2);

    auto loadTile = [&](int s) {
        const int k0 = s * 32;
        const uint32_t ab = sbase + (s & (NSTAGE - 1)) * STAGE_BYTES;
        const uint32_t bb = ab + AB_BYTES;
        #pragma unroll
        for (int i = 0; i < 2; i++) {           // A: 128 rows x 64B (4 chunks)
            int ch = tid + i * 256;
            int r = ch >> 2, c = ch & 3;
            cpasync16(ab + r * ROWB + c * 16,
                      g.A + (size_t)(bm + r) * g.lda + k0 + c * 8);
        }
        #pragma unroll
        for (int i = 0; i < 2; i++) {           // B: 128 rows x 64B
            int ch = tid + i * 256;
            int r = ch >> 2, c = ch & 3;
            cpasync16(bb + r * ROWB + c * 16,
                      g.Bt + (size_t)(g.bn + r) * g.ldbt + k0 + c * 8);
        }
        asm volatile("cp.async.commit_group;" ::);
    };

    float acc[4][4][4] = {};
    loadTile(0);
    loadTile(1);
    loadTile(2);

    for (int it = 0; it < nIter; ++it) {
        asm volatile("cp.async.wait_group 2;" ::);
        __syncthreads();
        if (it + 3 < nIter) loadTile(it + 3);

        const uint32_t stage = sbase + (it & (NSTAGE - 1)) * STAGE_BYTES;

        #pragma unroll
        for (int ks = 0; ks < 2; ks++) {
            const uint32_t kadd = stage + ks * 32;   // 16 halves = 32 bytes
            uint32_t af[4][4], bf[4][2];
            #pragma unroll
            for (int mt = 0; mt < 4; mt++)
                ldsm_x4(af[mt], kadd + a_off[mt]);
            #pragma unroll
            for (int p = 0; p < 2; p++) {
                uint32_t r[4];
                ldsm_x4(r, kadd + b_off[p]);
                bf[2 * p][0] = r[0]; bf[2 * p][1] = r[1];
                bf[2 * p + 1][0] = r[2]; bf[2 * p + 1][1] = r[3];
            }
            #pragma unroll
            for (int mt = 0; mt < 4; mt++)
                #pragma unroll
                for (int nt = 0; nt < 4; nt++)
                    mma_f16(acc[mt][nt],
                            af[mt][0], af[mt][1], af[mt][2], af[mt][3],
                            bf[nt][0], bf[nt][1]);
        }
    }

    // Epilogue
    #pragma unroll
    for (int mt = 0; mt < 4; mt++) {
        #pragma unroll
        for (int nt = 0; nt < 4; nt++) {
            const int gm0 = bm + wm + mt * 16 + lr;
            const int gn  = g.bn + wn + nt * 8 + lc * 2;
            #pragma unroll
            for (int hrow = 0; hrow < 2; hrow++) {
                const int gm = gm0 + hrow * 8;
                float vx = acc[mt][nt][hrow * 2 + 0];
                float vy = acc[mt][nt][hrow * 2 + 1];
                if (MODE == 0 || MODE == 2) {
                    vx += g.bias[gn];
                    vy += g.bias[gn + 1];
                }
                if (MODE == 0) {
                    vx = tanhf(vx); vy = tanhf(vy);
                    *(__half2*)&g_h[(size_t)gm * HH + gn] =
                        __floats2half2_rn(vx, vy);
                } else if (MODE == 1) {
                    *(float2*)&g_ux[(size_t)gm * NN + gn] =
                        make_float2(vx, vy);
                } else if (MODE == 2) {
                    *(float2*)&g_f[(size_t)gm * N2 + gn] =
                        make_float2(vx, vy);
                    if (gn < NN)
                        *(__half2*)&g_muh[(size_t)gm * NN + gn] =
                            __floats2half2_rn(vx, vy);
                } else {
                    *(float2*)&g_umu[(size_t)gm * NN + gn] =
                        make_float2(vx, vy);
                }
            }
        }
    }
}

// GEMM1: h = tanh(x@W1+b1) [16 col-tiles] fused with ux = x@Wv [2 tiles]
__global__ __launch_bounds__(256, 2) void k_gemm1(const float* __restrict__ b1)
{
    GCfg g;
    g.A = g_xh; g.lda = NN; g.K = NN;
    if (blockIdx.x < 16) {
        g.Bt = g_W1t; g.ldbt = NN; g.bias = b1; g.bn = blockIdx.x * 128;
        gemm_body<0>(g);
    } else {
        g.Bt = g_Wvt; g.ldbt = NN; g.bias = nullptr;
        g.bn = (blockIdx.x - 16) * 128;
        gemm_body<1>(g);
    }
}

// GEMM2: f = h@W2 + b2 (fp32) + fp16 mu copy
__global__ __launch_bounds__(256, 2) void k_gemm2(const float* __restrict__ b2)
{
    GCfg g;
    g.A = g_h; g.lda = HH; g.K = HH;
    g.Bt = g_W2t; g.ldbt = HH; g.bias = b2; g.bn = blockIdx.x * 128;
    gemm_body<2>(g);
}

// umu = mu @ Wv  (fp16 mu, dense lda=256)
__global__ __launch_bounds__(256, 2) void k_umu()
{
    GCfg g;
    g.A = g_muh; g.lda = NN; g.K = NN;
    g.Bt = g_Wvt; g.ldbt = NN; g.bias = nullptr; g.bn = blockIdx.x * 128;
    gemm_body<3>(g);
}

// ---------------------------------------------------------------------------
// Combined operand prep: all three weight transposes in ONE launch.
// ---------------------------------------------------------------------------
__device__ __forceinline__ void transpose_tile(
    const float* __restrict__ in, __half* __restrict__ out,
    int R, int C, int bx, int by)
{
    __shared__ float t[32][33];
    const int c0 = bx * 32, r0 = by * 32;
    #pragma unroll
    for (int j = 0; j < 4; j++)
        t[threadIdx.y + j * 8][threadIdx.x] =
            in[(size_t)(r0 + threadIdx.y + j * 8) * C + c0 + threadIdx.x];
    __syncthreads();
    #pragma unroll
    for (int j = 0; j < 4; j++)
        out[(size_t)(c0 + threadIdx.y + j * 8) * R + r0 + threadIdx.x] =
            __float2half_rn(t[threadIdx.x][threadIdx.y + j * 8]);
}

__global__ __launch_bounds__(256) void prep_weights_kernel(
    const float* __restrict__ W1, const float* __restrict__ W2,
    const float* __restrict__ Wv)
{
    const int b = blockIdx.x;
    if (b < 512) {          // W1 [256,2048] -> W1t; 64 x 8 tiles
        transpose_tile(W1, g_W1t, NN, HH, b & 63, b >> 6);
    } else if (b < 1536) {  // W2 [2048,512] -> W2t; 16 x 64 tiles
        const int bb = b - 512;
        transpose_tile(W2, g_W2t, HH, N2, bb & 15, bb >> 4);
    } else {                // Wv [256,256] -> Wvt; 8 x 8 tiles
        const int bb = b - 1536;
        transpose_tile(Wv, g_Wvt, NN, NN, bb & 7, bb >> 3);
    }
}

__global__ __launch_bounds__(256) void f32_to_h_kernel(
    const float4* __restrict__ in, __half2* __restrict__ out, int n4)
{
    int i = blockIdx.x * 256 + threadIdx.x;
    if (i < n4) {
        float4 v = in[i];
        out[i * 2 + 0] = __floats2half2_rn(v.x, v.y);
        out[i * 2 + 1] = __floats2half2_rn(v.z, v.w);
    }
}

// ---------------------------------------------------------------------------
__device__ __forceinline__ float blockReduce256(float v)
{
    #pragma unroll
    for (int o = 16; o > 0; o >>= 1)
        v += __shfl_down_sync(0xffffffffu, v, o);
    __shared__ float s[8];
    const int lane = threadIdx.x & 31;
    const int w = threadIdx.x >> 5;
    if (lane == 0) s[w] = v;
    __syncthreads();
    if (w == 0) {
        v = (lane < 8) ? s[lane] : 0.0f;
        #pragma unroll
        for (int o = 4; o > 0; o >>= 1)
            v += __shfl_down_sync(0xffffffffu, v, o);
    }
    __syncthreads();
    return v;
}

// Fused: V reductions + stabilized mean + sample + per-row logp
__global__ __launch_bounds__(256) void fused_epilogue_kernel(
    const float* __restrict__ y, const float* __restrict__ eps,
    float* __restrict__ out)
{
    const int r = blockIdx.x;
    const int n = threadIdx.x;
    const float a = g_ux[r * NN + n];
    const float b = g_umu[r * NN + n];
    const float sa = blockReduce256(a * a);
    const float sb = blockReduce256(b * b);
    __shared__ float sVx, sVmu;
    if (n == 0) { sVx = sa + 1e-3f; sVmu = sb + 1e-3f; }
    __syncthreads();

    const float mu = g_f[r * N2 + n];
    const float lv = g_f[r * N2 + NN + n];
    const float scale = fminf(0.99f * sVx, sVmu) / sVmu;  // bVx-relu(bVx-Vmu), /Vmu
    const float mus = mu * scale;
    const float var = expf(lv);
    const float sd  = expf(0.5f * lv);
    out[(size_t)r * NN + n] = mus + sd * eps[(size_t)r * NN + n];
    const float d = y[(size_t)r * NN + n] - mus;
    const float s = blockReduce256(lv + d * d / var);
    if (n == 0)
        g_rowlogp[r] = 0.5f * ((float)NN * LOG2PI + s);
}

__global__ __launch_bounds__(256) void finalsum_kernel(float* __restrict__ out,
                                                       int out_size)
{
    float s = 0.0f;
    for (int i = threadIdx.x; i < BB; i += 256)
        s += g_rowlogp[i];
    s = blockReduce256(s);
    if (threadIdx.x == 0)
        out[out_size - 1] = s;
}

// ---------------------------------------------------------------------------
extern "C" void kernel_launch(void* const* d_in, const int* in_sizes, int n_in,
                              void* d_out, int out_size)
{
    const float* x   = (const float*)d_in[0];
    const float* y   = (const float*)d_in[1];
    const float* eps = (const float*)d_in[2];
    const float* W1  = (const float*)d_in[3];
    const float* b1  = (const float*)d_in[4];
    const float* W2  = (const float*)d_in[5];
    const float* b2  = (const float*)d_in[6];
    const float* Wv  = (const float*)d_in[7];
    float* out = (float*)d_out;

    __half* xh;
    cudaGetSymbolAddress((void**)&xh, g_xh);

    cudaFuncSetAttribute(k_gemm1,
        cudaFuncAttributeMaxDynamicSharedMemorySize, SMEM_BYTES);
    cudaFuncSetAttribute(k_gemm2,
        cudaFuncAttributeMaxDynamicSharedMemorySize, SMEM_BYTES);
    cudaFuncSetAttribute(k_umu,
        cudaFuncAttributeMaxDynamicSharedMemorySize, SMEM_BYTES);

    // Operand prep
    f32_to_h_kernel<<<(BB * NN / 4 + 255) / 256, 256>>>(
        (const float4*)x, (__half2*)xh, BB * NN / 4);
    prep_weights_kernel<<<1600, dim3(32, 8)>>>(W1, W2, Wv);

    // h = tanh(x@W1+b1) [16 tiles] ++ ux = x@Wv [2 tiles]
    k_gemm1<<<dim3(18, BB / 128), 256, SMEM_BYTES>>>(b1);

    // f = h@W2 + b2 (+ fp16 mu copy)
    k_gemm2<<<dim3(N2 / 128, BB / 128), 256, SMEM_BYTES>>>(b2);

    // umu = mu @ Wv
    k_umu<<<dim3(NN / 128, BB / 128), 256, SMEM_BYTES>>>();

    // V reductions + sample + logp rows, then scalar sum
    fused_epilogue_kernel<<<BB, 256>>>(y, eps, out);
    finalsum_kernel<<<1, 256>>>(out, out_size);
}

// round 17
// speedup vs baseline: 1.0631x; 1.0631x over previous
#include <cuda_runtime.h>
#include <cuda_fp16.h>
#include <math.h>
#include <stdint.h>

// Problem constants
#define BB 8192
#define NN 256
#define HH 2048
#define N2 512
#define LOG2PI 1.8378770664093453f

// Smem: BK=64. A tile 128 rows x 72 halves (144B rows, 16B-aligned), B same.
#define ASTR 72
#define ROWB 144
#define AB_BYTES (128 * ROWB)           // 18432 per operand tile
#define STAGE_BYTES (2 * AB_BYTES)      // 36864
#define NSTAGE 3
#define SMEM_BYTES (NSTAGE * STAGE_BYTES)   // 110592

// Scratch (static __device__ — no runtime allocation)
__device__ __half g_h[BB * HH];     // tanh(x@W1+b1), fp16
__device__ float  g_f[BB * N2];     // [mu | logvar], fp32
__device__ __half g_muh[BB * NN];   // fp16 copy of mu (dense, lda=256)
__device__ float  g_ux[BB * NN];
__device__ float  g_umu[BB * NN];
__device__ float  g_rowlogp[BB];
__device__ __half g_xh[BB * NN];    // fp16 x
__device__ __half g_W1t[HH * NN];   // W1^T [2048,256]
__device__ __half g_W2t[N2 * HH];   // W2^T [512,2048]
__device__ __half g_Wvt[NN * NN];   // Wv^T [256,256]

// ---------------------------------------------------------------------------
__device__ __forceinline__ void mma_f16(float (&c)[4],
    uint32_t a0, uint32_t a1, uint32_t a2, uint32_t a3,
    uint32_t b0, uint32_t b1)
{
    asm volatile(
        "mma.sync.aligned.m16n8k16.row.col.f32.f16.f16.f32 "
        "{%0,%1,%2,%3}, {%4,%5,%6,%7}, {%8,%9}, {%0,%1,%2,%3};"
        : "+f"(c[0]), "+f"(c[1]), "+f"(c[2]), "+f"(c[3])
        : "r"(a0), "r"(a1), "r"(a2), "r"(a3), "r"(b0), "r"(b1));
}

__device__ __forceinline__ void ldsm_x4(uint32_t (&r)[4], uint32_t addr)
{
    asm volatile(
        "ldmatrix.sync.aligned.m8n8.x4.shared.b16 {%0,%1,%2,%3}, [%4];"
        : "=r"(r[0]), "=r"(r[1]), "=r"(r[2]), "=r"(r[3]) : "r"(addr));
}

__device__ __forceinline__ void cpasync16(uint32_t dst_smem, const void* src) {
    asm volatile("cp.async.cg.shared.global [%0], [%1], 16;"
                 :: "r"(dst_smem), "l"(src));
}

__device__ __forceinline__ uint32_t smem_u32(const void* p) {
    uint32_t a;
    asm("{ .reg .u64 t; cvta.to.shared.u64 t, %1; cvt.u32.u64 %0, t; }"
        : "=r"(a) : "l"(p));
    return a;
}

// ---------------------------------------------------------------------------
// fp16 MMA GEMM body. Block 128x128, BK=64, 8 warps, warp tile 64x32.
// 3-stage cp.async ring, wait_group 1, ONE barrier per iteration.
// MODE: 0 = h (bias+tanh, fp16), 1 = ux (fp32), 2 = f (bias, fp32 + fp16 mu),
//       3 = umu (fp32)
// ---------------------------------------------------------------------------
struct GCfg {
    const __half* A;  int lda;
    const __half* Bt; int ldbt;
    const float* bias;
    int bn, K;
};

template<int MODE>
__device__ __forceinline__ void gemm_body(const GCfg& g)
{
    extern __shared__ char smem[];
    const uint32_t sbase = smem_u32(smem);
    const int tid  = threadIdx.x;
    const int lane = tid & 31;
    const int w    = tid >> 5;
    const int wm   = (w >> 2) * 64;
    const int wn   = (w & 3) * 32;
    const int bm   = blockIdx.y * 128;
    const int lr   = lane >> 2;
    const int lc   = lane & 3;
    const int nIter = g.K / 64;

    // ldmatrix per-lane offsets (bytes within a stage)
    const int a_row = (lane & 7) + ((lane >> 3) & 1) * 8;
    const int a_k   = ((lane >> 4) & 1) * 8;
    uint32_t a_off[4];
    #pragma unroll
    for (int mt = 0; mt < 4; mt++)
        a_off[mt] = (uint32_t)(((wm + mt * 16 + a_row) * ASTR + a_k) * 2);
    const int b_row = ((lane >> 4) & 1) * 8 + (lane & 7);
    const int b_k   = ((lane >> 3) & 1) * 8;
    uint32_t b_off[2];
    #pragma unroll
    for (int p = 0; p < 2; p++)
        b_off[p] = (uint32_t)(AB_BYTES + ((wn + p * 16 + b_row) * ASTR + b_k) * 2);

    int stageIdx[3];   // avoid % in hot loop
    stageIdx[0] = 0; stageIdx[1] = 1; stageIdx[2] = 2;

    auto loadTile = [&](int s) {
        const int k0 = s * 64;
        const uint32_t ab = sbase + (s % NSTAGE) * STAGE_BYTES;
        const uint32_t bb = ab + AB_BYTES;
        #pragma unroll
        for (int i = 0; i < 4; i++) {           // A: 128 rows x 128B
            int ch = tid + i * 256;
            int r = ch >> 3, c = ch & 7;
            cpasync16(ab + r * ROWB + c * 16,
                      g.A + (size_t)(bm + r) * g.lda + k0 + c * 8);
        }
        #pragma unroll
        for (int i = 0; i < 4; i++) {           // B: 128 rows x 128B
            int ch = tid + i * 256;
            int r = ch >> 3, c = ch & 7;
            cpasync16(bb + r * ROWB + c * 16,
                      g.Bt + (size_t)(g.bn + r) * g.ldbt + k0 + c * 8);
        }
        asm volatile("cp.async.commit_group;" ::);
    };

    float acc[4][4][4] = {};
    loadTile(0);
    loadTile(1);

    int cur = 0;
    for (int it = 0; it < nIter; ++it) {
        asm volatile("cp.async.wait_group 1;" ::);
        __syncthreads();                         // single barrier per iter
        if (it + 2 < nIter) loadTile(it + 2);

        const uint32_t stage = sbase + cur * STAGE_BYTES;
        cur = (cur == NSTAGE - 1) ? 0 : cur + 1;

        #pragma unroll
        for (int ks = 0; ks < 4; ks++) {
            const uint32_t kadd = stage + ks * 32;   // 16 halves = 32 bytes
            uint32_t af[4][4], bf[4][2];
            #pragma unroll
            for (int mt = 0; mt < 4; mt++)
                ldsm_x4(af[mt], kadd + a_off[mt]);
            #pragma unroll
            for (int p = 0; p < 2; p++) {
                uint32_t r[4];
                ldsm_x4(r, kadd + b_off[p]);
                bf[2 * p][0] = r[0]; bf[2 * p][1] = r[1];
                bf[2 * p + 1][0] = r[2]; bf[2 * p + 1][1] = r[3];
            }
            #pragma unroll
            for (int mt = 0; mt < 4; mt++)
                #pragma unroll
                for (int nt = 0; nt < 4; nt++)
                    mma_f16(acc[mt][nt],
                            af[mt][0], af[mt][1], af[mt][2], af[mt][3],
                            bf[nt][0], bf[nt][1]);
        }
    }

    // Epilogue
    #pragma unroll
    for (int mt = 0; mt < 4; mt++) {
        #pragma unroll
        for (int nt = 0; nt < 4; nt++) {
            const int gm0 = bm + wm + mt * 16 + lr;
            const int gn  = g.bn + wn + nt * 8 + lc * 2;
            #pragma unroll
            for (int hrow = 0; hrow < 2; hrow++) {
                const int gm = gm0 + hrow * 8;
                float vx = acc[mt][nt][hrow * 2 + 0];
                float vy = acc[mt][nt][hrow * 2 + 1];
                if (MODE == 0 || MODE == 2) {
                    vx += g.bias[gn];
                    vy += g.bias[gn + 1];
                }
                if (MODE == 0) {
                    vx = tanhf(vx); vy = tanhf(vy);
                    *(__half2*)&g_h[(size_t)gm * HH + gn] =
                        __floats2half2_rn(vx, vy);
                } else if (MODE == 1) {
                    *(float2*)&g_ux[(size_t)gm * NN + gn] =
                        make_float2(vx, vy);
                } else if (MODE == 2) {
                    *(float2*)&g_f[(size_t)gm * N2 + gn] =
                        make_float2(vx, vy);
                    if (gn < NN)
                        *(__half2*)&g_muh[(size_t)gm * NN + gn] =
                            __floats2half2_rn(vx, vy);
                } else {
                    *(float2*)&g_umu[(size_t)gm * NN + gn] =
                        make_float2(vx, vy);
                }
            }
        }
    }
}

// GEMM1: h = tanh(x@W1+b1) [16 col-tiles] fused with ux = x@Wv [2 tiles]
__global__ __launch_bounds__(256, 2) void k_gemm1(const float* __restrict__ b1)
{
    GCfg g;
    g.A = g_xh; g.lda = NN; g.K = NN;
    if (blockIdx.x < 16) {
        g.Bt = g_W1t; g.ldbt = NN; g.bias = b1; g.bn = blockIdx.x * 128;
        gemm_body<0>(g);
    } else {
        g.Bt = g_Wvt; g.ldbt = NN; g.bias = nullptr;
        g.bn = (blockIdx.x - 16) * 128;
        gemm_body<1>(g);
    }
}

// GEMM2: f = h@W2 + b2 (fp32) + fp16 mu copy
__global__ __launch_bounds__(256, 2) void k_gemm2(const float* __restrict__ b2)
{
    GCfg g;
    g.A = g_h; g.lda = HH; g.K = HH;
    g.Bt = g_W2t; g.ldbt = HH; g.bias = b2; g.bn = blockIdx.x * 128;
    gemm_body<2>(g);
}

// umu = mu @ Wv  (fp16 mu, dense lda=256)
__global__ __launch_bounds__(256, 2) void k_umu()
{
    GCfg g;
    g.A = g_muh; g.lda = NN; g.K = NN;
    g.Bt = g_Wvt; g.ldbt = NN; g.bias = nullptr; g.bn = blockIdx.x * 128;
    gemm_body<3>(g);
}

// ---------------------------------------------------------------------------
// Combined operand prep: all three weight transposes in ONE launch.
// ---------------------------------------------------------------------------
__device__ __forceinline__ void transpose_tile(
    const float* __restrict__ in, __half* __restrict__ out,
    int R, int C, int bx, int by)
{
    __shared__ float t[32][33];
    const int c0 = bx * 32, r0 = by * 32;
    #pragma unroll
    for (int j = 0; j < 4; j++)
        t[threadIdx.y + j * 8][threadIdx.x] =
            in[(size_t)(r0 + threadIdx.y + j * 8) * C + c0 + threadIdx.x];
    __syncthreads();
    #pragma unroll
    for (int j = 0; j < 4; j++)
        out[(size_t)(c0 + threadIdx.y + j * 8) * R + r0 + threadIdx.x] =
            __float2half_rn(t[threadIdx.x][threadIdx.y + j * 8]);
}

__global__ __launch_bounds__(256) void prep_weights_kernel(
    const float* __restrict__ W1, const float* __restrict__ W2,
    const float* __restrict__ Wv)
{
    const int b = blockIdx.x;
    if (b < 512) {          // W1 [256,2048] -> W1t; 64 x 8 tiles
        transpose_tile(W1, g_W1t, NN, HH, b & 63, b >> 6);
    } else if (b < 1536) {  // W2 [2048,512] -> W2t; 16 x 64 tiles
        const int bb = b - 512;
        transpose_tile(W2, g_W2t, HH, N2, bb & 15, bb >> 4);
    } else {                // Wv [256,256] -> Wvt; 8 x 8 tiles
        const int bb = b - 1536;
        transpose_tile(Wv, g_Wvt, NN, NN, bb & 7, bb >> 3);
    }
}

__global__ __launch_bounds__(256) void f32_to_h_kernel(
    const float4* __restrict__ in, __half2* __restrict__ out, int n4)
{
    int i = blockIdx.x * 256 + threadIdx.x;
    if (i < n4) {
        float4 v = in[i];
        out[i * 2 + 0] = __floats2half2_rn(v.x, v.y);
        out[i * 2 + 1] = __floats2half2_rn(v.z, v.w);
    }
}

// ---------------------------------------------------------------------------
__device__ __forceinline__ float blockReduce256(float v)
{
    #pragma unroll
    for (int o = 16; o > 0; o >>= 1)
        v += __shfl_down_sync(0xffffffffu, v, o);
    __shared__ float s[8];
    const int lane = threadIdx.x & 31;
    const int w = threadIdx.x >> 5;
    if (lane == 0) s[w] = v;
    __syncthreads();
    if (w == 0) {
        v = (lane < 8) ? s[lane] : 0.0f;
        #pragma unroll
        for (int o = 4; o > 0; o >>= 1)
            v += __shfl_down_sync(0xffffffffu, v, o);
    }
    __syncthreads();
    return v;
}

// Fused: V reductions + stabilized mean + sample + per-row logp
__global__ __launch_bounds__(256) void fused_epilogue_kernel(
    const float* __restrict__ y, const float* __restrict__ eps,
    float* __restrict__ out)
{
    const int r = blockIdx.x;
    const int n = threadIdx.x;
    const float a = g_ux[r * NN + n];
    const float b = g_umu[r * NN + n];
    const float sa = blockReduce256(a * a);
    const float sb = blockReduce256(b * b);
    __shared__ float sVx, sVmu;
    if (n == 0) { sVx = sa + 1e-3f; sVmu = sb + 1e-3f; }
    __syncthreads();

    const float mu = g_f[r * N2 + n];
    const float lv = g_f[r * N2 + NN + n];
    const float scale = fminf(0.99f * sVx, sVmu) / sVmu;  // bVx-relu(bVx-Vmu), /Vmu
    const float mus = mu * scale;
    const float var = expf(lv);
    const float sd  = expf(0.5f * lv);
    out[(size_t)r * NN + n] = mus + sd * eps[(size_t)r * NN + n];
    const float d = y[(size_t)r * NN + n] - mus;
    const float s = blockReduce256(lv + d * d / var);
    if (n == 0)
        g_rowlogp[r] = 0.5f * ((float)NN * LOG2PI + s);
}

__global__ __launch_bounds__(256) void finalsum_kernel(float* __restrict__ out,
                                                       int out_size)
{
    float s = 0.0f;
    for (int i = threadIdx.x; i < BB; i += 256)
        s += g_rowlogp[i];
    s = blockReduce256(s);
    if (threadIdx.x == 0)
        out[out_size - 1] = s;
}

// ---------------------------------------------------------------------------
extern "C" void kernel_launch(void* const* d_in, const int* in_sizes, int n_in,
                              void* d_out, int out_size)
{
    const float* x   = (const float*)d_in[0];
    const float* y   = (const float*)d_in[1];
    const float* eps = (const float*)d_in[2];
    const float* W1  = (const float*)d_in[3];
    const float* b1  = (const float*)d_in[4];
    const float* W2  = (const float*)d_in[5];
    const float* b2  = (const float*)d_in[6];
    const float* Wv  = (const float*)d_in[7];
    float* out = (float*)d_out;

    __half* xh;
    cudaGetSymbolAddress((void**)&xh, g_xh);

    cudaFuncSetAttribute(k_gemm1,
        cudaFuncAttributeMaxDynamicSharedMemorySize, SMEM_BYTES);
    cudaFuncSetAttribute(k_gemm2,
        cudaFuncAttributeMaxDynamicSharedMemorySize, SMEM_BYTES);
    cudaFuncSetAttribute(k_umu,
        cudaFuncAttributeMaxDynamicSharedMemorySize, SMEM_BYTES);

    // Operand prep
    f32_to_h_kernel<<<(BB * NN / 4 + 255) / 256, 256>>>(
        (const float4*)x, (__half2*)xh, BB * NN / 4);
    prep_weights_kernel<<<1600, dim3(32, 8)>>>(W1, W2, Wv);

    // h = tanh(x@W1+b1) [16 tiles] ++ ux = x@Wv [2 tiles]
    k_gemm1<<<dim3(18, BB / 128), 256, SMEM_BYTES>>>(b1);

    // f = h@W2 + b2 (+ fp16 mu copy)
    k_gemm2<<<dim3(N2 / 128, BB / 128), 256, SMEM_BYTES>>>(b2);

    // umu = mu @ Wv
    k_umu<<<dim3(NN / 128, BB / 128), 256, SMEM_BYTES>>>();

    // V reductions + sample + logp rows, then scalar sum
    fused_epilogue_kernel<<<BB, 256>>>(y, eps, out);
    finalsum_kernel<<<1, 256>>>(out, out_size);
}